// round 3
// baseline (speedup 1.0000x reference)
#include <cuda_runtime.h>
#include <cstdint>
#include <cstddef>

#define B_ 8
#define N_ 4096
#define M_ 4096
#define C_ 256

#define SPLITS 8
#define KM_PER_SPLIT 16      // 16 * 32 = 512 m-rows per split

#define STA 136              // stride (words) for [32][128] k-major tiles  (136 mod 32 = 8)
#define STQ 36               // stride (words) for [128][32] n-major q tile (36 mod 32 = 4)

// Scratch (static device arrays; no allocations allowed)
__device__ uint32_t g_qn[B_ * N_ * C_];            // tf32(q * rq / N)
__device__ uint32_t g_kn[B_ * M_ * C_];            // tf32(k * rk)
__device__ float    g_kvp[SPLITS * B_ * C_ * C_];  // split-K partials
__device__ uint32_t g_kv[B_ * C_ * C_];            // reduced kv, tf32

__device__ __forceinline__ uint32_t f2tf(float x) {
    uint32_t r;
    asm("cvt.rna.tf32.f32 %0, %1;" : "=r"(r) : "f"(x));
    return r;
}

__device__ __forceinline__ void mma8(float c[4], const uint32_t a[4], const uint32_t b[2]) {
    asm volatile(
        "mma.sync.aligned.m16n8k8.row.col.f32.tf32.tf32.f32 "
        "{%0,%1,%2,%3}, {%4,%5,%6,%7}, {%8,%9}, {%0,%1,%2,%3};\n"
        : "+f"(c[0]), "+f"(c[1]), "+f"(c[2]), "+f"(c[3])
        : "r"(a[0]), "r"(a[1]), "r"(a[2]), "r"(a[3]),
          "r"(b[0]), "r"(b[1]));
}

__device__ __forceinline__ void cp16(void* smem, const void* gmem) {
    uint32_t s = (uint32_t)__cvta_generic_to_shared(smem);
    asm volatile("cp.async.cg.shared.global [%0], [%1], 16;\n" :: "r"(s), "l"(gmem));
}
__device__ __forceinline__ void cp_commit() { asm volatile("cp.async.commit_group;\n" ::: "memory"); }
template <int NN>
__device__ __forceinline__ void cp_wait() { asm volatile("cp.async.wait_group %0;\n" :: "n"(NN) : "memory"); }

// ---------------------------------------------------------------------------
// Kernel 1 (prep): one warp per row.
//   q rows: rq = 1/(N*max(||q||,eps));  qn = tf32(q*rq)
//   k rows: rk = 1/max(||k||,eps);      kn = tf32(k*rk)
// Pure streaming pass: 134 MB; all tf32 conversion paid here once per element.
// ---------------------------------------------------------------------------
__global__ __launch_bounds__(256) void prep_kernel(const float* __restrict__ q,
                                                   const float* __restrict__ k) {
    const int gw = (blockIdx.x * blockDim.x + threadIdx.x) >> 5;   // row id
    const int lane = threadIdx.x & 31;
    const float* src;
    uint32_t* dst;
    float post;
    if (gw < B_ * N_) {
        src = q + (size_t)gw * C_;
        dst = g_qn + (size_t)gw * C_;
        post = 1.0f / (float)N_;
    } else {
        const int r = gw - B_ * N_;
        src = k + (size_t)r * C_;
        dst = g_kn + (size_t)r * C_;
        post = 1.0f;
    }
    float4 a = *(const float4*)(src + lane * 4);
    float4 b = *(const float4*)(src + 128 + lane * 4);
    float ss = a.x * a.x + a.y * a.y + a.z * a.z + a.w * a.w
             + b.x * b.x + b.y * b.y + b.z * b.z + b.w * b.w;
#pragma unroll
    for (int o = 16; o > 0; o >>= 1) ss += __shfl_xor_sync(0xffffffffu, ss, o);
    // 1/max(sqrt(ss), 1e-12), with the post scale folded in
    float rn = (ss > 1e-24f) ? rsqrtf(ss) : 1e12f;
    rn *= post;
    uint4 o0, o1;
    o0.x = f2tf(a.x * rn); o0.y = f2tf(a.y * rn); o0.z = f2tf(a.z * rn); o0.w = f2tf(a.w * rn);
    o1.x = f2tf(b.x * rn); o1.y = f2tf(b.y * rn); o1.z = f2tf(b.z * rn); o1.w = f2tf(b.w * rn);
    *(uint4*)(dst + lane * 4)       = o0;
    *(uint4*)(dst + 128 + lane * 4) = o1;
}

// ---------------------------------------------------------------------------
// Kernel 2: split-K partials of kv[b][c][d] = sum_m kn[b][m][c] * v[b][m][d]
// CTA tile 128(c) x 128(d), BK=32, 2-stage cp.async pipeline.
// A (kn) already tf32 -> no cvt. B (v) raw fp32 -> 8 cvt per kk.
// ---------------------------------------------------------------------------
__global__ __launch_bounds__(256) void kv_kernel(const float* __restrict__ v) {
    extern __shared__ uint32_t sm[];
    uint32_t* As = sm;                    // [2][32*STA] tf32
    float*    Bs = (float*)(sm + 2 * 32 * STA);   // [2][32*STA] raw fp32

    const int bz = blockIdx.z;       // b*8 + split
    const int b  = bz >> 3;
    const int sp = bz & 7;
    const int c0 = blockIdx.y * 128;
    const int d0 = blockIdx.x * 128;
    const int m_base = sp * (KM_PER_SPLIT * 32);

    const int t = threadIdx.x, lane = t & 31, wid = t >> 5;
    const int g = lane >> 2, tig = lane & 3;
    const int wc = (wid >> 2) * 64;
    const int wd = (wid & 3) * 32;

    const int lr = t >> 3;           // 0..31 (tile row)
    const int lq = (t & 7) * 4;      // word col base, iterate +32

    const uint32_t* kb = g_kn + (size_t)b * M_ * C_ + c0;
    const float*    vb = v    + (size_t)b * M_ * C_ + d0;

    // prologue: stage 0
    {
        const int m0 = m_base;
#pragma unroll
        for (int i = 0; i < 4; i++) {
            cp16(&As[lr * STA + lq + i * 32], kb + (size_t)(m0 + lr) * C_ + lq + i * 32);
            cp16(&Bs[lr * STA + lq + i * 32], vb + (size_t)(m0 + lr) * C_ + lq + i * 32);
        }
        cp_commit();
    }

    float acc[4][4][4] = {};

#pragma unroll 1
    for (int km = 0; km < KM_PER_SPLIT; km++) {
        const int cur = km & 1;
        if (km + 1 < KM_PER_SPLIT) {
            const int nxt = cur ^ 1;
            const int m0 = m_base + (km + 1) * 32;
            uint32_t* An = &As[nxt * 32 * STA];
            float*    Bn = &Bs[nxt * 32 * STA];
#pragma unroll
            for (int i = 0; i < 4; i++) {
                cp16(&An[lr * STA + lq + i * 32], kb + (size_t)(m0 + lr) * C_ + lq + i * 32);
                cp16(&Bn[lr * STA + lq + i * 32], vb + (size_t)(m0 + lr) * C_ + lq + i * 32);
            }
            cp_commit();
            cp_wait<1>();
        } else {
            cp_wait<0>();
        }
        __syncthreads();

        const uint32_t* Ac = &As[cur * 32 * STA];
        const float*    Bc = &Bs[cur * 32 * STA];
#pragma unroll
        for (int kk = 0; kk < 4; kk++) {
            const int k8 = kk * 8;
            uint32_t af[4][4];
            uint32_t bf[4][2];
#pragma unroll
            for (int mt = 0; mt < 4; mt++) {
                const int row = wc + mt * 16 + g;
                const uint32_t* a0 = &Ac[(k8 + tig) * STA + row];
                const uint32_t* a1 = &Ac[(k8 + tig + 4) * STA + row];
                af[mt][0] = a0[0];
                af[mt][1] = a0[8];
                af[mt][2] = a1[0];
                af[mt][3] = a1[8];
            }
#pragma unroll
            for (int nt = 0; nt < 4; nt++) {
                const int col = wd + nt * 8 + g;
                bf[nt][0] = f2tf(Bc[(k8 + tig) * STA + col]);
                bf[nt][1] = f2tf(Bc[(k8 + tig + 4) * STA + col]);
            }
#pragma unroll
            for (int mt = 0; mt < 4; mt++)
#pragma unroll
                for (int nt = 0; nt < 4; nt++)
                    mma8(acc[mt][nt], af[mt], bf[nt]);
        }
        __syncthreads();
    }

    float* kvp = g_kvp + ((size_t)sp * B_ + b) * C_ * C_;
#pragma unroll
    for (int mt = 0; mt < 4; mt++)
#pragma unroll
        for (int nt = 0; nt < 4; nt++) {
            const int c = c0 + wc + mt * 16 + g;
            const int d = d0 + wd + nt * 8 + tig * 2;
            float2 v0 = make_float2(acc[mt][nt][0], acc[mt][nt][1]);
            float2 v1 = make_float2(acc[mt][nt][2], acc[mt][nt][3]);
            *(float2*)&kvp[(size_t)c * C_ + d]       = v0;
            *(float2*)&kvp[(size_t)(c + 8) * C_ + d] = v1;
        }
}

// ---------------------------------------------------------------------------
// Kernel 2b: reduce the SPLITS partials into g_kv, emitting tf32.
// ---------------------------------------------------------------------------
__global__ __launch_bounds__(256) void reduce_kernel() {
    const int i = blockIdx.x * blockDim.x + threadIdx.x;       // float4 index
    const float4* p = (const float4*)g_kvp;
    const int stride = B_ * C_ * C_ / 4;
    float4 a = p[i];
#pragma unroll
    for (int s = 1; s < SPLITS; s++) {
        float4 x = p[s * stride + i];
        a.x += x.x; a.y += x.y; a.z += x.z; a.w += x.w;
    }
    uint4 o;
    o.x = f2tf(a.x); o.y = f2tf(a.y); o.z = f2tf(a.z); o.w = f2tf(a.w);
    ((uint4*)g_kv)[i] = o;
}

// ---------------------------------------------------------------------------
// Kernel 3: out[b][n][d] = sum_c qn[b][n][c] * kv[b][c][d]
// CTA tile 128(n) x 128(d), BK=32 over c, fully unrolled 8-step K loop.
// Both operands pre-converted tf32 -> inner loop is pure LDS + MMA.
// ---------------------------------------------------------------------------
__global__ __launch_bounds__(256) void ctx_kernel(float* __restrict__ out) {
    extern __shared__ uint32_t sm[];
    uint32_t* As = sm;                        // [2][128*STQ]  n-major
    uint32_t* Bs = sm + 2 * 128 * STQ;        // [2][32*STA]

    const int b  = blockIdx.z;
    const int n0 = blockIdx.y * 128;
    const int d0 = blockIdx.x * 128;

    const int t = threadIdx.x, lane = t & 31, wid = t >> 5;
    const int g = lane >> 2, tig = lane & 3;
    const int wn = (wid >> 2) * 64;
    const int wd = (wid & 3) * 32;

    const int ar = t >> 3;           // base row for A loads (0..31), +32*i
    const int aq = (t & 7) * 4;      // word col (0..28)
    const int br = t >> 3;           // B tile row 0..31
    const int bq = (t & 7) * 4;

    const uint32_t* qb  = g_qn + ((size_t)b * N_ + n0) * C_;
    const uint32_t* kvb = g_kv + (size_t)b * C_ * C_ + d0;

    // prologue stage 0 (c-chunk 0)
    {
#pragma unroll
        for (int i = 0; i < 4; i++)
            cp16(&As[(ar + 32 * i) * STQ + aq], qb + (size_t)(ar + 32 * i) * C_ + aq);
#pragma unroll
        for (int i = 0; i < 4; i++)
            cp16(&Bs[br * STA + bq + i * 32], kvb + (size_t)br * C_ + bq + i * 32);
        cp_commit();
    }

    float acc[4][4][4] = {};
    const int KM = C_ / 32;   // 8

#pragma unroll
    for (int km = 0; km < KM; km++) {
        const int cur = km & 1;
        if (km + 1 < KM) {
            const int nxt = cur ^ 1;
            const int cb = (km + 1) * 32;
            uint32_t* An = &As[nxt * 128 * STQ];
            uint32_t* Bn = &Bs[nxt * 32 * STA];
#pragma unroll
            for (int i = 0; i < 4; i++)
                cp16(&An[(ar + 32 * i) * STQ + aq], qb + (size_t)(ar + 32 * i) * C_ + cb + aq);
#pragma unroll
            for (int i = 0; i < 4; i++)
                cp16(&Bn[br * STA + bq + i * 32], kvb + (size_t)(cb + br) * C_ + bq + i * 32);
            cp_commit();
            cp_wait<1>();
        } else {
            cp_wait<0>();
        }
        __syncthreads();

        const uint32_t* Ac = &As[cur * 128 * STQ];
        const uint32_t* Bc = &Bs[cur * 32 * STA];
#pragma unroll
        for (int kk = 0; kk < 4; kk++) {
            const int k8 = kk * 8;
            uint32_t af[4][4];
            uint32_t bf[4][2];
#pragma unroll
            for (int mt = 0; mt < 4; mt++) {
                const int row = wn + mt * 16 + g;
                af[mt][0] = Ac[(size_t)row * STQ + k8 + tig];
                af[mt][1] = Ac[(size_t)(row + 8) * STQ + k8 + tig];
                af[mt][2] = Ac[(size_t)row * STQ + k8 + tig + 4];
                af[mt][3] = Ac[(size_t)(row + 8) * STQ + k8 + tig + 4];
            }
#pragma unroll
            for (int nt = 0; nt < 4; nt++) {
                const int col = wd + nt * 8 + g;
                bf[nt][0] = Bc[(k8 + tig) * STA + col];
                bf[nt][1] = Bc[(k8 + tig + 4) * STA + col];
            }
#pragma unroll
            for (int mt = 0; mt < 4; mt++)
#pragma unroll
                for (int nt = 0; nt < 4; nt++)
                    mma8(acc[mt][nt], af[mt], bf[nt]);
        }
        __syncthreads();
    }

#pragma unroll
    for (int mt = 0; mt < 4; mt++)
#pragma unroll
        for (int nt = 0; nt < 4; nt++) {
            const int n = n0 + wn + mt * 16 + g;
            const int d = d0 + wd + nt * 8 + tig * 2;
            float2 v0 = make_float2(acc[mt][nt][0], acc[mt][nt][1]);
            float2 v1 = make_float2(acc[mt][nt][2], acc[mt][nt][3]);
            *(float2*)&out[((size_t)b * N_ + n) * C_ + d]       = v0;
            *(float2*)&out[((size_t)b * N_ + n + 8) * C_ + d]   = v1;
        }
}

// ---------------------------------------------------------------------------
extern "C" void kernel_launch(void* const* d_in, const int* in_sizes, int n_in,
                              void* d_out, int out_size) {
    const float* q = (const float*)d_in[0];
    const float* k = (const float*)d_in[1];
    const float* v = (const float*)d_in[2];
    float* out = (float*)d_out;

    const int smem_kv  = (2 * 32 * STA + 2 * 32 * STA) * 4;            // ~70 KB
    const int smem_ctx = (2 * 128 * STQ + 2 * 32 * STA) * 4;           // ~72 KB
    cudaFuncSetAttribute(kv_kernel,  cudaFuncAttributeMaxDynamicSharedMemorySize, smem_kv);
    cudaFuncSetAttribute(ctx_kernel, cudaFuncAttributeMaxDynamicSharedMemorySize, smem_ctx);

    // 1) normalize + tf32-convert q and k (cvt paid once per element)
    prep_kernel<<<(B_ * N_ + B_ * M_) / 8, 256>>>(q, k);
    // 2) split-K partial kv = kn^T @ v
    kv_kernel<<<dim3(C_ / 128, C_ / 128, B_ * SPLITS), 256, smem_kv>>>(v);
    // 2b) reduce partials -> tf32 kv
    reduce_kernel<<<(B_ * C_ * C_ / 4) / 256, 256>>>();
    // 3) out = qn @ kv
    ctx_kernel<<<dim3(C_ / 128, N_ / 128, B_), 256, smem_ctx>>>(out);
}